// round 15
// baseline (speedup 1.0000x reference)
#include <cuda_runtime.h>
#include <cuda_fp16.h>

// FixedFoveatedSensor: out[b,c,h,w] = sum_s bilinear(img, warp(pos_s)) * det_s / sum_s det_s
// img: (4,3,1024,1024) f32, t: (1,) f32, jitter: (16,256,256,2) f32, out: (4,3,256,256) f32
//
// R12 structure (best so far) + occupancy push:
// Stage: planar fp32 -> flat interleaved fp16 buffers b0 (ch0-7, 16B/px), b1 (ch8-11, 8B/px).
// Gather: warp = 2 px x 16 spp, 1 thread = 1 full sample; per corner 1 LDG.128 + 1 LDG.64;
// jitter staged through smem via coalesced block load. NEW: __launch_bounds__(256, 8)
// caps regs at 32 -> 8 blocks/SM (100% theoretical occupancy, was 75%).

#define SPP 16
#define SH 256
#define SW 256
#define NBC 12
#define NVALS 13
#define PIX_PER_BLOCK 16
#define BLOCK 256
#define IMG_H 1024
#define IMG_W 1024
#define NPIX (IMG_H * IMG_W)

__device__ uint4 g_b0[NPIX];   // 16 MB: ch0-7 fp16
__device__ uint2 g_b1[NPIX];   // 8 MB:  ch8-11 fp16

// ---------------- stage: 4 pixels per thread ----------------
__global__ __launch_bounds__(256)
void stage_kernel(const float* __restrict__ img)
{
    const int px0 = (blockIdx.x * 256 + threadIdx.x) * 4;

    float4 v[NBC];
#pragma unroll
    for (int c = 0; c < NBC; c++)
        v[c] = *reinterpret_cast<const float4*>(img + (size_t)c * NPIX + px0);

    const float* f = reinterpret_cast<const float*>(v);     // f[c*4 + k]

#pragma unroll
    for (int k = 0; k < 4; k++) {
        unsigned u0[4], u1[2];
#pragma unroll
        for (int q = 0; q < 4; q++) {
            const __half2 h = __floats2half2_rn(f[(2 * q) * 4 + k], f[(2 * q + 1) * 4 + k]);
            u0[q] = *reinterpret_cast<const unsigned*>(&h);
        }
#pragma unroll
        for (int q = 0; q < 2; q++) {
            const __half2 h = __floats2half2_rn(f[(8 + 2 * q) * 4 + k], f[(9 + 2 * q) * 4 + k]);
            u1[q] = *reinterpret_cast<const unsigned*>(&h);
        }
        g_b0[px0 + k] = make_uint4(u0[0], u0[1], u0[2], u0[3]);
        g_b1[px0 + k] = make_uint2(u1[0], u1[1]);
    }
}

// ---------------- gather ----------------
__global__ __launch_bounds__(BLOCK, 8)
void ffs_kernel(const float* __restrict__ t,
                const float* __restrict__ jitter,
                float* __restrict__ out)
{
    __shared__ float2 jit_s[SPP][PIX_PER_BLOCK + 1];
    __shared__ float  red[BLOCK * NVALS];
    __shared__ float  det_s[PIX_PER_BLOCK];

    const int tid = threadIdx.x;
    const int pixelBase = blockIdx.x * PIX_PER_BLOCK;

    // coalesced jitter load: 16 spp-rows x 16 px x 8 B = one 128B line per row
    {
        const int s = tid >> 4;
        const int p = tid & 15;
        jit_s[s][p] = ((const float2*)jitter)[(size_t)s * (SH * SW) + pixelBase + p];
    }
    __syncthreads();

    const int spp = tid & 15;
    const int pin = tid >> 4;
    const int pixel = pixelBase + pin;
    const int h = pixel >> 8;
    const int w = pixel & 255;

    const float tt    = t[0];
    const float s_inv = 1.0f / tanhf(tt);
    const float step  = 2.0f / 256.0f;

    const float2 jit = jit_s[spp][pin];
    const float posx = fmaf(jit.x, step, -1.0f + (float)w * step);
    const float posy = fmaf(jit.y, step, -1.0f + (float)h * step);

    const float thx = tanhf(tt * posx);
    const float thy = tanhf(tt * posy);
    const float ddx = tt * (1.0f - thx * thx) * s_inv;
    const float ddy = tt * (1.0f - thy * thy) * s_inv;
    const float det = ddx * ddy;

    float gx = (thx * s_inv + 1.0f) * 512.0f - 0.5f;
    float gy = (thy * s_inv + 1.0f) * 512.0f - 0.5f;
    gx = fminf(fmaxf(gx, 0.0f), 1023.0f);
    gy = fminf(fmaxf(gy, 0.0f), 1023.0f);
    const float x0f = floorf(gx);
    const float y0f = floorf(gy);
    const float fx = gx - x0f;
    const float fy = gy - y0f;
    const int x0 = (int)x0f;
    const int y0 = (int)y0f;
    const int x1 = min(x0 + 1, IMG_W - 1);
    const int y1 = min(y0 + 1, IMG_H - 1);

    const float w11 = fx * fy * det;
    const float w01 = fx * det - w11;
    const float w10 = fy * det - w11;
    const float w00 = det - w01 - w10 - w11;

    const int i00 = y0 * IMG_W + x0;
    const int i01 = y0 * IMG_W + x1;
    const int i10 = y1 * IMG_W + x0;
    const int i11 = y1 * IMG_W + x1;

    float acc[NBC];
#pragma unroll
    for (int j = 0; j < NBC; j++) acc[j] = 0.0f;

    {
        const int   ii[4] = { i00, i01, i10, i11 };
        const float ww[4] = { w00, w01, w10, w11 };
#pragma unroll
        for (int c = 0; c < 4; c++) {
            const uint4 a = g_b0[ii[c]];
            const uint2 b = g_b1[ii[c]];
            const unsigned uu[6] = { a.x, a.y, a.z, a.w, b.x, b.y };
            const float wc = ww[c];
#pragma unroll
            for (int q = 0; q < 6; q++) {
                const float2 f = __half22float2(*reinterpret_cast<const __half2*>(&uu[q]));
                acc[2 * q]     = fmaf(f.x, wc, acc[2 * q]);
                acc[2 * q + 1] = fmaf(f.y, wc, acc[2 * q + 1]);
            }
        }
    }

#pragma unroll
    for (int j = 0; j < NBC; j++) red[tid * NVALS + j] = acc[j];
    red[tid * NVALS + NBC] = det;
    __syncthreads();

    // 16 px x 13 values = 208 sum-threads, each sums its value over 16 spp
    float sum = 0.0f;
    int p = 0, j = 0;
    if (tid < PIX_PER_BLOCK * NVALS) {
        p = tid / NVALS;
        j = tid - p * NVALS;
        const float* b2 = red + (p * SPP) * NVALS + j;
#pragma unroll
        for (int k = 0; k < SPP; k++) sum += b2[k * NVALS];
        if (j == NBC) det_s[p] = sum;
    }
    __syncthreads();

    if (tid < PIX_PER_BLOCK * NVALS && j < NBC) {
        const int opix = pixelBase + p;
        out[(size_t)j * (SH * SW) + opix] = sum / det_s[p];
    }
}

extern "C" void kernel_launch(void* const* d_in, const int* in_sizes, int n_in,
                              void* d_out, int out_size)
{
    const float* img    = (const float*)d_in[0];
    const float* t      = (const float*)d_in[1];
    const float* jitter = (const float*)d_in[2];
    float* out          = (float*)d_out;

    stage_kernel<<<NPIX / (256 * 4), 256>>>(img);
    ffs_kernel<<<(SH * SW) / PIX_PER_BLOCK, BLOCK>>>(t, jitter, out);
}

// round 17
// speedup vs baseline: 1.5322x; 1.5322x over previous
#include <cuda_runtime.h>
#include <cuda_fp16.h>

// FixedFoveatedSensor: out[b,c,h,w] = sum_s bilinear(img, warp(pos_s)) * det_s / sum_s det_s
// img: (4,3,1024,1024) f32, t: (1,) f32, jitter: (16,256,256,2) f32, out: (4,3,256,256) f32
//
// R12 structure (best: 35.3us) + (a) HFMA2 half2 accumulation in the bilinear inner loop,
// (b) PDL via cudaLaunchAttributeProgrammaticStreamSerialization: gather's prologue
// (jitter load + tanh) overlaps the stage kernel's tail; cudaGridDependencySynchronize()
// guards the first read of the staged buffers.

#define SPP 16
#define SH 256
#define SW 256
#define NBC 12
#define NVALS 13
#define PIX_PER_BLOCK 16
#define BLOCK 256
#define IMG_H 1024
#define IMG_W 1024
#define NPIX (IMG_H * IMG_W)

__device__ uint4 g_b0[NPIX];   // 16 MB: ch0-7 fp16
__device__ uint2 g_b1[NPIX];   // 8 MB:  ch8-11 fp16

// ---------------- stage: 4 pixels per thread ----------------
__global__ __launch_bounds__(256)
void stage_kernel(const float* __restrict__ img)
{
    const int px0 = (blockIdx.x * 256 + threadIdx.x) * 4;

    float4 v[NBC];
#pragma unroll
    for (int c = 0; c < NBC; c++)
        v[c] = *reinterpret_cast<const float4*>(img + (size_t)c * NPIX + px0);

    const float* f = reinterpret_cast<const float*>(v);     // f[c*4 + k]

#pragma unroll
    for (int k = 0; k < 4; k++) {
        unsigned u0[4], u1[2];
#pragma unroll
        for (int q = 0; q < 4; q++) {
            const __half2 h = __floats2half2_rn(f[(2 * q) * 4 + k], f[(2 * q + 1) * 4 + k]);
            u0[q] = *reinterpret_cast<const unsigned*>(&h);
        }
#pragma unroll
        for (int q = 0; q < 2; q++) {
            const __half2 h = __floats2half2_rn(f[(8 + 2 * q) * 4 + k], f[(9 + 2 * q) * 4 + k]);
            u1[q] = *reinterpret_cast<const unsigned*>(&h);
        }
        g_b0[px0 + k] = make_uint4(u0[0], u0[1], u0[2], u0[3]);
        g_b1[px0 + k] = make_uint2(u1[0], u1[1]);
    }
}

// ---------------- gather ----------------
__global__ __launch_bounds__(BLOCK)
void ffs_kernel(const float* __restrict__ t,
                const float* __restrict__ jitter,
                float* __restrict__ out)
{
    __shared__ float2 jit_s[SPP][PIX_PER_BLOCK + 1];
    __shared__ float  red[BLOCK * NVALS];
    __shared__ float  det_s[PIX_PER_BLOCK];

    const int tid = threadIdx.x;
    const int pixelBase = blockIdx.x * PIX_PER_BLOCK;

    // coalesced jitter load (harness input, independent of stage kernel)
    {
        const int s = tid >> 4;
        const int p = tid & 15;
        jit_s[s][p] = ((const float2*)jitter)[(size_t)s * (SH * SW) + pixelBase + p];
    }
    __syncthreads();

    const int spp = tid & 15;
    const int pin = tid >> 4;
    const int pixel = pixelBase + pin;
    const int h = pixel >> 8;
    const int w = pixel & 255;

    const float tt    = t[0];
    const float s_inv = 1.0f / tanhf(tt);
    const float step  = 2.0f / 256.0f;

    const float2 jit = jit_s[spp][pin];
    const float posx = fmaf(jit.x, step, -1.0f + (float)w * step);
    const float posy = fmaf(jit.y, step, -1.0f + (float)h * step);

    const float thx = tanhf(tt * posx);
    const float thy = tanhf(tt * posy);
    const float ddx = tt * (1.0f - thx * thx) * s_inv;
    const float ddy = tt * (1.0f - thy * thy) * s_inv;
    const float det = ddx * ddy;

    float gx = (thx * s_inv + 1.0f) * 512.0f - 0.5f;
    float gy = (thy * s_inv + 1.0f) * 512.0f - 0.5f;
    gx = fminf(fmaxf(gx, 0.0f), 1023.0f);
    gy = fminf(fmaxf(gy, 0.0f), 1023.0f);
    const float x0f = floorf(gx);
    const float y0f = floorf(gy);
    const float fx = gx - x0f;
    const float fy = gy - y0f;
    const int x0 = (int)x0f;
    const int y0 = (int)y0f;
    const int x1 = min(x0 + 1, IMG_W - 1);
    const int y1 = min(y0 + 1, IMG_H - 1);

    const float w11 = fx * fy * det;
    const float w01 = fx * det - w11;
    const float w10 = fy * det - w11;
    const float w00 = det - w01 - w10 - w11;

    const int i00 = y0 * IMG_W + x0;
    const int i01 = y0 * IMG_W + x1;
    const int i10 = y1 * IMG_W + x0;
    const int i11 = y1 * IMG_W + x1;

    // wait for staged image (PDL barrier) only now — prologue above overlapped with stage
#if __CUDA_ARCH__ >= 900
    cudaGridDependencySynchronize();
#endif

    __half2 acc2[6];
#pragma unroll
    for (int q = 0; q < 6; q++) acc2[q] = __half2half2(__ushort_as_half(0));

    {
        const int   ii[4] = { i00, i01, i10, i11 };
        const float ww[4] = { w00, w01, w10, w11 };
#pragma unroll
        for (int c = 0; c < 4; c++) {
            const uint4 a = g_b0[ii[c]];
            const uint2 b = g_b1[ii[c]];
            const unsigned uu[6] = { a.x, a.y, a.z, a.w, b.x, b.y };
            const __half2 wch = __float2half2_rn(ww[c]);
#pragma unroll
            for (int q = 0; q < 6; q++) {
                const __half2 vh = *reinterpret_cast<const __half2*>(&uu[q]);
                acc2[q] = __hfma2(vh, wch, acc2[q]);
            }
        }
    }

#pragma unroll
    for (int q = 0; q < 6; q++) {
        const float2 f = __half22float2(acc2[q]);
        red[tid * NVALS + 2 * q]     = f.x;
        red[tid * NVALS + 2 * q + 1] = f.y;
    }
    red[tid * NVALS + NBC] = det;
    __syncthreads();

    // 16 px x 13 values = 208 sum-threads, each sums its value over 16 spp
    float sum = 0.0f;
    int p = 0, j = 0;
    if (tid < PIX_PER_BLOCK * NVALS) {
        p = tid / NVALS;
        j = tid - p * NVALS;
        const float* b2 = red + (p * SPP) * NVALS + j;
#pragma unroll
        for (int k = 0; k < SPP; k++) sum += b2[k * NVALS];
        if (j == NBC) det_s[p] = sum;
    }
    __syncthreads();

    if (tid < PIX_PER_BLOCK * NVALS && j < NBC) {
        const int opix = pixelBase + p;
        out[(size_t)j * (SH * SW) + opix] = sum / det_s[p];
    }
}

extern "C" void kernel_launch(void* const* d_in, const int* in_sizes, int n_in,
                              void* d_out, int out_size)
{
    const float* img    = (const float*)d_in[0];
    const float* t      = (const float*)d_in[1];
    const float* jitter = (const float*)d_in[2];
    float* out          = (float*)d_out;

    stage_kernel<<<NPIX / (256 * 4), 256>>>(img);

    // PDL secondary: overlap stage tail with gather prologue
    cudaLaunchConfig_t cfg = {};
    cfg.gridDim  = dim3((SH * SW) / PIX_PER_BLOCK, 1, 1);
    cfg.blockDim = dim3(BLOCK, 1, 1);
    cfg.dynamicSmemBytes = 0;
    cudaLaunchAttribute attrs[1];
    attrs[0].id = cudaLaunchAttributeProgrammaticStreamSerialization;
    attrs[0].val.programmaticStreamSerializationAllowed = 1;
    cfg.attrs = attrs;
    cfg.numAttrs = 1;
    cudaLaunchKernelEx(&cfg, ffs_kernel, t, jitter, out);
}